// round 1
// baseline (speedup 1.0000x reference)
#include <cuda_runtime.h>

// Problem constants (fixed shapes)
#define BB 8
#define GG 64
#define CC 192
#define HH 256
#define WW 256
#define HWN 65536          // H*W
#define OO 256             // width2

// Scratch: per (b,g): {A0, A1, A2, C} where A_j = bn1_scale[g]*softmax_j,
// C = bn1_beta[g] - bn1_scale[g]*bn1_mean[g]
__device__ float4 g_attnW[BB * GG];

// ---------------------------------------------------------------------------
// Kernel 1: attention statistics.
// One block per (b,g). Each block streams 3 channels (768 KB), computes per
// 4x4 window: max over window for the 3 channels (xq) and sum (xk*16), and
// accumulates the 3x3 Gram matrix. Epilogue: scale, collapse with attnconv_w,
// softmax, fold bn1, write float4 to scratch.
// ---------------------------------------------------------------------------
__global__ __launch_bounds__(256) void attn_kernel(
    const float* __restrict__ x,
    const float* __restrict__ aw,      // (G,3)
    const float* __restrict__ bn1_g, const float* __restrict__ bn1_b,
    const float* __restrict__ bn1_m, const float* __restrict__ bn1_v)
{
    const int bg = blockIdx.x;             // b*G + g
    const int g  = bg & 63;
    const float* xb = x + (size_t)bg * 3 * HWN;   // (b*G+g)*3 = b*C + g*3

    const int t    = threadIdx.x;
    const int lane = t & 31;
    const int warp = t >> 5;

    float acc[9];
#pragma unroll
    for (int q = 0; q < 9; q++) acc[q] = 0.0f;

    // 4096 windows (64x64), 256 threads, 16 iterations
#pragma unroll 1
    for (int it = 0; it < 16; it++) {
        const int wIdx = it * 256 + t;
        const int wy = wIdx >> 6;
        const int wx = wIdx & 63;
        float m[3], s[3];
#pragma unroll
        for (int ch = 0; ch < 3; ch++) {
            const float4* pc = (const float4*)(xb + (size_t)ch * HWN + (wy * 4) * WW + wx * 4);
            float4 r0 = __ldcs(pc);
            float4 r1 = __ldcs(pc + (WW / 4));
            float4 r2 = __ldcs(pc + 2 * (WW / 4));
            float4 r3 = __ldcs(pc + 3 * (WW / 4));
            float mx = fmaxf(fmaxf(fmaxf(r0.x, r0.y), fmaxf(r0.z, r0.w)),
                      fmaxf(fmaxf(fmaxf(r1.x, r1.y), fmaxf(r1.z, r1.w)),
                      fmaxf(fmaxf(fmaxf(r2.x, r2.y), fmaxf(r2.z, r2.w)),
                            fmaxf(fmaxf(r3.x, r3.y), fmaxf(r3.z, r3.w)))));
            float sm = (r0.x + r0.y + r0.z + r0.w) + (r1.x + r1.y + r1.z + r1.w)
                     + (r2.x + r2.y + r2.z + r2.w) + (r3.x + r3.y + r3.z + r3.w);
            m[ch] = mx;
            s[ch] = sm;
        }
#pragma unroll
        for (int i = 0; i < 3; i++)
#pragma unroll
            for (int j = 0; j < 3; j++)
                acc[i * 3 + j] += m[i] * s[j];
    }

    // Block reduction of 9 accumulators
    __shared__ float red[9][8];
    __shared__ float fin[9];
#pragma unroll
    for (int q = 0; q < 9; q++) {
        float v = acc[q];
#pragma unroll
        for (int off = 16; off > 0; off >>= 1)
            v += __shfl_xor_sync(0xFFFFFFFFu, v, off);
        if (lane == 0) red[q][warp] = v;
    }
    __syncthreads();
    if (t < 9) {
        float s = 0.0f;
#pragma unroll
        for (int w = 0; w < 8; w++) s += red[t][w];
        fin[t] = s;
    }
    __syncthreads();

    if (t == 0) {
        // attn[i][j] = fin[i*3+j] * (1/16 avg) * (4/h scale) = fin/1024
        const float w0 = aw[g * 3 + 0], w1 = aw[g * 3 + 1], w2 = aw[g * 3 + 2];
        float r0 = (fin[0] * w0 + fin[3] * w1 + fin[6] * w2) * (1.0f / 1024.0f);
        float r1 = (fin[1] * w0 + fin[4] * w1 + fin[7] * w2) * (1.0f / 1024.0f);
        float r2 = (fin[2] * w0 + fin[5] * w1 + fin[8] * w2) * (1.0f / 1024.0f);
        float mx = fmaxf(r0, fmaxf(r1, r2));
        float e0 = __expf(r0 - mx), e1 = __expf(r1 - mx), e2 = __expf(r2 - mx);
        float inv = 1.0f / (e0 + e1 + e2);
        // fold bn1 scale into softmax weights
        float sc = bn1_g[g] * rsqrtf(bn1_v[g] + 1e-5f);
        float cc = bn1_b[g] - sc * bn1_m[g];
        float4 o;
        o.x = sc * e0 * inv;
        o.y = sc * e1 * inv;
        o.z = sc * e2 * inv;
        o.w = cc;
        g_attnW[bg] = o;
    }
}

// ---------------------------------------------------------------------------
// Kernel 2: fused weighted-sum + bn1 + relu + 1x1 conv + bn2.
// Block tile: all 256 outputs x 128 positions, 512 threads.
// Phase A: ygr[64][128] in smem (relu(bn1(sum_j a_j * x_j))).
// Phase B: K=64 GEMM, 8o x 8n micro-tile per thread, W via __ldg (L1-resident).
// ---------------------------------------------------------------------------
__global__ __launch_bounds__(512, 1) void fused_kernel(
    const float* __restrict__ x,
    const float* __restrict__ convw,   // (O, G) row-major
    const float* __restrict__ bn2_g, const float* __restrict__ bn2_b,
    const float* __restrict__ bn2_m, const float* __restrict__ bn2_v,
    float* __restrict__ out)
{
    __shared__ float ygr[64][128];

    const int b  = blockIdx.y;
    const int n0 = blockIdx.x * 128;
    const int t  = threadIdx.x;

    // ---- Phase A ----
    {
        const int pos = t & 127;
        const int gq  = t >> 7;                       // 0..3
        const float* xb = x + (size_t)b * CC * HWN + n0 + pos;
        const float4* awb = g_attnW + b * GG;
#pragma unroll
        for (int it = 0; it < 16; it++) {
            const int g = it * 4 + gq;
            const float4 a = __ldg(awb + g);
            const float* p = xb + (size_t)(g * 3) * HWN;
            float x0 = __ldcs(p);
            float x1 = __ldcs(p + HWN);
            float x2 = __ldcs(p + 2 * HWN);
            float y = fmaf(a.x, x0, fmaf(a.y, x1, fmaf(a.z, x2, a.w)));
            ygr[g][pos] = fmaxf(y, 0.0f);
        }
    }
    __syncthreads();

    // ---- Phase B: GEMM ----
    const int nt = t & 15;        // 16 n-groups of 8
    const int ot = t >> 4;        // 32 o-groups of 8
    const int nn = nt * 8;
    const int oo = ot * 8;

    float acc[8][8];
#pragma unroll
    for (int i = 0; i < 8; i++)
#pragma unroll
        for (int j = 0; j < 8; j++) acc[i][j] = 0.0f;

    const float* wp = convw + oo * GG;

#pragma unroll
    for (int k = 0; k < 64; k += 2) {
        float2 wv[8];
#pragma unroll
        for (int i = 0; i < 8; i++)
            wv[i] = __ldg((const float2*)(wp + i * GG + k));
        float4 ya0 = *(const float4*)&ygr[k][nn];
        float4 ya1 = *(const float4*)&ygr[k][nn + 4];
        float4 yb0 = *(const float4*)&ygr[k + 1][nn];
        float4 yb1 = *(const float4*)&ygr[k + 1][nn + 4];
        const float ya[8] = {ya0.x, ya0.y, ya0.z, ya0.w, ya1.x, ya1.y, ya1.z, ya1.w};
        const float yb[8] = {yb0.x, yb0.y, yb0.z, yb0.w, yb1.x, yb1.y, yb1.z, yb1.w};
#pragma unroll
        for (int i = 0; i < 8; i++) {
#pragma unroll
            for (int j = 0; j < 8; j++) {
                acc[i][j] = fmaf(wv[i].x, ya[j], acc[i][j]);
                acc[i][j] = fmaf(wv[i].y, yb[j], acc[i][j]);
            }
        }
    }

    // ---- Epilogue: bn2 fold + store ----
    float* ob = out + (size_t)b * OO * HWN + n0 + nn;
#pragma unroll
    for (int i = 0; i < 8; i++) {
        const int o = oo + i;
        float sc = __ldg(bn2_g + o) * rsqrtf(__ldg(bn2_v + o) + 1e-5f);
        float bi = __ldg(bn2_b + o) - sc * __ldg(bn2_m + o);
        float4 v0, v1;
        v0.x = fmaf(acc[i][0], sc, bi);
        v0.y = fmaf(acc[i][1], sc, bi);
        v0.z = fmaf(acc[i][2], sc, bi);
        v0.w = fmaf(acc[i][3], sc, bi);
        v1.x = fmaf(acc[i][4], sc, bi);
        v1.y = fmaf(acc[i][5], sc, bi);
        v1.z = fmaf(acc[i][6], sc, bi);
        v1.w = fmaf(acc[i][7], sc, bi);
        float* po = ob + (size_t)o * HWN;
        *(float4*)po = v0;
        *(float4*)(po + 4) = v1;
    }
}

extern "C" void kernel_launch(void* const* d_in, const int* in_sizes, int n_in,
                              void* d_out, int out_size)
{
    const float* x     = (const float*)d_in[0];
    const float* aw    = (const float*)d_in[1];
    const float* bn1_g = (const float*)d_in[2];
    const float* bn1_b = (const float*)d_in[3];
    const float* bn1_m = (const float*)d_in[4];
    const float* bn1_v = (const float*)d_in[5];
    const float* convw = (const float*)d_in[6];
    const float* bn2_g = (const float*)d_in[7];
    const float* bn2_b = (const float*)d_in[8];
    const float* bn2_m = (const float*)d_in[9];
    const float* bn2_v = (const float*)d_in[10];
    float* out = (float*)d_out;

    attn_kernel<<<BB * GG, 256>>>(x, aw, bn1_g, bn1_b, bn1_m, bn1_v);
    fused_kernel<<<dim3(HWN / 128, BB), 512>>>(x, convw, bn2_g, bn2_b, bn2_m, bn2_v, out);
}